// round 12
// baseline (speedup 1.0000x reference)
#include <cuda_runtime.h>
#include <climits>

// Problem shape (fixed): B=4, C=1, D=64, H=256, W=256
#define SLICES      256
#define UNIT_SPLIT  8                       // units per slice
#define NUNITS      (SLICES * UNIT_SPLIT)   // 2048
#define UNIT_F4     2048                    // float4 per unit (8192 elems)
#define ITERS       8                       // float4 per thread per unit
#define THREADS     256
#define NWARPS      8
#define GRID        592                     // 148 SMs * 4
#define TOTAL_ELEMS 16777216.0f
#define NBOX_ELEMS  1024.0f
#define LN2F        0.6931471805599453f

// Scratch (no allocation allowed).
// g_bbox: encoded maxes per slice: [0]=256-minR, [1]=maxR+1, [2]=256-minC, [3]=maxC+1; 0 = empty.
// Zero-initialized at load; tail resets to zero after every run (graph-replay safe).
__device__ int      g_bbox[SLICES][4] = {};
__device__ float    g_segW[NUNITS * NWARPS];   // per unit-warp seg partials (fully overwritten each run)
__device__ unsigned g_work  = 0;
__device__ unsigned g_count = 0;

__global__ void __launch_bounds__(THREADS) fused_kernel(
    const float4* __restrict__ x4p, const float4* __restrict__ t4p,
    const float*  __restrict__ tgt, float* __restrict__ out)
{
    const int tid = threadIdx.x;
    const int wid = tid >> 5, lid = tid & 31;

    __shared__ unsigned s_u[2];

    // ---- work-stealing prologue ----
    if (tid == 0) s_u[0] = atomicAdd(&g_work, 1u);
    __syncthreads();
    unsigned u = s_u[0];
    int par = 1;

    while (u < NUNITS) {
        // prefetch next unit index (latency hidden behind this unit's processing)
        if (tid == 0) s_u[par] = atomicAdd(&g_work, 1u);

        // ---- process unit u: slice = u>>3, part = u&7, rows [part*32, part*32+32) ----
        const int part = (int)(u & (UNIT_SPLIT - 1));
        const int slice = (int)(u >> 3);
        const float4* __restrict__ xb = x4p + (size_t)u * UNIT_F4 + tid;
        const float4* __restrict__ tb = t4p + (size_t)u * UNIT_F4 + tid;

        float cm0 = -1.0f, cm1 = -1.0f, cm2 = -1.0f, cm3 = -1.0f;
        float aL0 = 0.0f, aL1 = 0.0f;     // Σ (max(x,0) - x·t)
        float accL2 = 0.0f;               // Σ log2(Π(1+e^-|x|))
        unsigned rmask = 0;

        float4 xc = __ldcs(xb);
        float4 tc = __ldcs(tb);

        #pragma unroll
        for (int k = 0; k < ITERS; ++k) {
            float4 xn, tn;
            if (k < ITERS - 1) {
                xn = __ldcs(xb + THREADS * (k + 1));
                tn = __ldcs(tb + THREADS * (k + 1));
            }
            const float4 xv = xc;
            const float4 tv = tc;

            float e0 = __expf(-fabsf(xv.x));
            float e1 = __expf(-fabsf(xv.y));
            float a01 = 1.0f + e0;
            float p01 = __fmaf_rn(e1, a01, a01);
            float e2 = __expf(-fabsf(xv.z));
            float e3 = __expf(-fabsf(xv.w));
            float a23 = 1.0f + e2;
            float p23 = __fmaf_rn(e3, a23, a23);
            accL2 += __log2f(p01 * p23);

            aL0 += fmaxf(xv.x, 0.0f);
            aL0  = __fmaf_rn(-xv.x, tv.x, aL0);
            aL1 += fmaxf(xv.y, 0.0f);
            aL1  = __fmaf_rn(-xv.y, tv.y, aL1);
            aL0 += fmaxf(xv.z, 0.0f);
            aL0  = __fmaf_rn(-xv.z, tv.z, aL0);
            aL1 += fmaxf(xv.w, 0.0f);
            aL1  = __fmaf_rn(-xv.w, tv.w, aL1);

            cm0 = fmaxf(cm0, xv.x);
            cm1 = fmaxf(cm1, xv.y);
            cm2 = fmaxf(cm2, xv.z);
            cm3 = fmaxf(cm3, xv.w);
            float m4 = fmaxf(fmaxf(xv.x, xv.y), fmaxf(xv.z, xv.w));
            if (m4 > 0.0f) rmask |= (1u << k);

            xc = xn;
            tc = tn;
        }

        // per-thread bbox, max-encoded (0 = empty)
        int eMinR, eMaxR, eMinC, eMaxC;
        {
            const int rb = part * 32 + (tid >> 6);      // rows rb + 4k
            if (rmask) {
                eMinR = 256 - (rb + 4 * (__ffs(rmask) - 1));
                eMaxR = rb + 4 * (31 - __clz(rmask)) + 1;
            } else { eMinR = 0; eMaxR = 0; }

            const int cb = (tid & 63) << 2;
            unsigned cmsk = (cm0 > 0.0f ? 1u : 0u) | (cm1 > 0.0f ? 2u : 0u)
                          | (cm2 > 0.0f ? 4u : 0u) | (cm3 > 0.0f ? 8u : 0u);
            if (cmsk) {
                eMinC = 256 - (cb + (__ffs(cmsk) - 1));
                eMaxC = cb + (31 - __clz(cmsk)) + 1;
            } else { eMinC = 0; eMaxC = 0; }
        }

        float segw = (aL0 + aL1) + LN2F * accL2;

        // warp reduction: sum seg, max the four encodings
        #pragma unroll
        for (int off = 16; off > 0; off >>= 1) {
            segw += __shfl_xor_sync(0xFFFFFFFFu, segw, off);
            eMinR = max(eMinR, __shfl_xor_sync(0xFFFFFFFFu, eMinR, off));
            eMaxR = max(eMaxR, __shfl_xor_sync(0xFFFFFFFFu, eMaxR, off));
            eMinC = max(eMinC, __shfl_xor_sync(0xFFFFFFFFu, eMinC, off));
            eMaxC = max(eMaxC, __shfl_xor_sync(0xFFFFFFFFu, eMaxC, off));
        }
        if (lid == 0) {
            if (eMaxR > 0) {   // only touch atomics when this warp saw positives
                atomicMax(&g_bbox[slice][0], eMinR);
                atomicMax(&g_bbox[slice][1], eMaxR);
                atomicMax(&g_bbox[slice][2], eMinC);
                atomicMax(&g_bbox[slice][3], eMaxC);
            }
            g_segW[u * NWARPS + wid] = segw;
        }

        __syncthreads();
        u = s_u[par];
        par ^= 1;
    }

    // ---- last-block-finishes tail ----
    __shared__ bool s_isLast;
    __threadfence();
    if (tid == 0) {
        unsigned c = atomicAdd(&g_count, 1u);
        s_isLast = (c == GRID - 1);
    }
    __syncthreads();
    if (!s_isLast) return;

    // seg: thread t sums 64 fixed slots (deterministic order)
    float segT = 0.0f;
    #pragma unroll 8
    for (int i = 0; i < (NUNITS * NWARPS) / THREADS; ++i)
        segT += __ldcg(&g_segW[tid * ((NUNITS * NWARPS) / THREADS) + i]);

    // bbox loss: thread s handles slice s
    float l = 0.0f;
    {
        const int s = tid;
        int a = __ldcg(&g_bbox[s][0]);
        int b = __ldcg(&g_bbox[s][1]);
        int c = __ldcg(&g_bbox[s][2]);
        int d = __ldcg(&g_bbox[s][3]);

        float bx, by, bw, bh;
        if (b == 0) {                    // empty mask
            bx = 0.0f; by = 0.0f; bw = 256.0f; bh = 256.0f;
        } else {
            int minR = 256 - a, maxR = b - 1;
            int minC = 256 - c, maxC = d - 1;
            bx = (float)minC; by = (float)minR;
            bw = (float)(maxC - minC); bh = (float)(maxR - minR);
        }

        float pred[4] = {bx, by, bw, bh};
        #pragma unroll
        for (int j = 0; j < 4; ++j) {
            float dd = pred[j] - tgt[s * 4 + j];
            float ad = fabsf(dd);
            l += (ad < 1.0f) ? 0.5f * dd * dd : ad - 0.5f;
        }

        // reset for next graph replay
        g_bbox[s][0] = 0; g_bbox[s][1] = 0; g_bbox[s][2] = 0; g_bbox[s][3] = 0;
    }

    #pragma unroll
    for (int off = 16; off > 0; off >>= 1) {
        segT += __shfl_xor_sync(0xFFFFFFFFu, segT, off);
        l    += __shfl_xor_sync(0xFFFFFFFFu, l,    off);
    }
    __shared__ float t_seg[NWARPS], t_box[NWARPS];
    if (lid == 0) { t_seg[wid] = segT; t_box[wid] = l; }
    __syncthreads();
    if (tid == 0) {
        float fs = 0.0f, fb = 0.0f;
        #pragma unroll
        for (int w = 0; w < NWARPS; ++w) { fs += t_seg[w]; fb += t_box[w]; }
        out[0] = fs / TOTAL_ELEMS;
        out[1] = fb / NBOX_ELEMS;
        g_work  = 0;                     // reset for next graph replay
        g_count = 0;
    }
}

extern "C" void kernel_launch(void* const* d_in, const int* in_sizes, int n_in,
                              void* d_out, int out_size)
{
    const float4* x4 = (const float4*)d_in[0];   // model_output
    const float4* t4 = (const float4*)d_in[1];   // target_masks
    const float*  tb = (const float*)d_in[2];    // target_bboxes
    float* out = (float*)d_out;

    fused_kernel<<<GRID, THREADS>>>(x4, t4, tb, out);
}

// round 13
// speedup vs baseline: 1.4208x; 1.4208x over previous
#include <cuda_runtime.h>
#include <climits>

// Problem shape (fixed): B=4, C=1, D=64, H=256, W=256
#define SLICES      256                 // B*D
#define SPLIT       2                   // parts per slice
#define NBLOCKS     (SLICES * SPLIT)    // 512  -> single wave
#define THREADS     256
#define PART_F4     8192                // float4 per part (32768 elems)
#define ITERS       32                  // stages of 256 float4
#define STAGES      4                   // smem ring depth
#define ROWS_PER_PART 128
#define TOTAL_ELEMS 16777216.0f
#define NBOX_ELEMS  1024.0f
#define LN2F        0.6931471805599453f
#define PF_CHUNK    65536               // L2 prefetch chunk (bytes)

// Scratch (no allocation allowed) — partials per block
__device__ float        g_seg[NBLOCKS];
__device__ int4         g_box[NBLOCKS];   // x=minR, y=maxR, z=minC, w=maxC
__device__ unsigned int g_count = 0;

__device__ __forceinline__ void cpa16(void* sdst, const void* gsrc) {
    unsigned sa = (unsigned)__cvta_generic_to_shared(sdst);
    asm volatile("cp.async.cg.shared.global [%0], [%1], 16;" :: "r"(sa), "l"(gsrc) : "memory");
}
__device__ __forceinline__ void cpa_commit() {
    asm volatile("cp.async.commit_group;" ::: "memory");
}
__device__ __forceinline__ void cpa_wait2() {
    asm volatile("cp.async.wait_group 2;" ::: "memory");
}
__device__ __forceinline__ void l2_prefetch(const void* g, unsigned bytes) {
    asm volatile("cp.async.bulk.prefetch.L2.global [%0], %1;" :: "l"(g), "r"(bytes) : "memory");
}

__global__ void __launch_bounds__(THREADS) fused_kernel(
    const float4* __restrict__ x4p, const float4* __restrict__ t4p,
    const float*  __restrict__ tgt, float* __restrict__ out)
{
    __shared__ __align__(16) float4 s_x[STAGES][THREADS];
    __shared__ __align__(16) float4 s_t[STAGES][THREADS];

    const int blk  = blockIdx.x;            // blk = slice*SPLIT + part
    const int tid  = threadIdx.x;
    const int part = blk & (SPLIT - 1);
    const int rowBase = part * ROWS_PER_PART;

    const float4* __restrict__ xb = x4p + (size_t)blk * PART_F4 + tid;
    const float4* __restrict__ tb = t4p + (size_t)blk * PART_F4 + tid;

    // ---- bulk L2 prefetch of this block's whole part (x: 128KB, t: 128KB) ----
    if (tid == 0) {
        const char* xg = (const char*)(x4p + (size_t)blk * PART_F4);
        const char* tg = (const char*)(t4p + (size_t)blk * PART_F4);
        #pragma unroll
        for (int c = 0; c < (PART_F4 * 16) / PF_CHUNK; ++c) {
            l2_prefetch(xg + (size_t)c * PF_CHUNK, PF_CHUNK);
            l2_prefetch(tg + (size_t)c * PF_CHUNK, PF_CHUNK);
        }
    }

    // Accumulators. Columns are FIXED per thread (stride 256 ≡ 0 mod 64).
    float cm0 = -1.0f, cm1 = -1.0f, cm2 = -1.0f, cm3 = -1.0f;
    float aL0 = 0.0f, aL1 = 0.0f;       // Σ (max(x,0) - x·t), two chains
    float accL2 = 0.0f;                 // Σ log2(Π(1+e^-|x|))
    unsigned rmask = 0;                 // bit k: any(x>0) in k-th visited row (32 rows)

    // ---- prologue: stages 0..2 in flight ----
    #pragma unroll
    for (int s = 0; s < STAGES - 1; ++s) {
        cpa16(&s_x[s][tid], xb + s * THREADS);
        cpa16(&s_t[s][tid], tb + s * THREADS);
        cpa_commit();
    }

    // Each thread reads ONLY data it staged itself -> no __syncthreads needed.
    // Group j contains stage j; wait_group 2 at iter k => stage k resident.
    #pragma unroll 4
    for (int k = 0; k < ITERS; ++k) {
        cpa_wait2();
        const int slot = k & (STAGES - 1);
        const float4 xv = s_x[slot][tid];
        const float4 tv = s_t[slot][tid];

        if (k + STAGES - 1 < ITERS) {
            const int ns = (k + STAGES - 1) & (STAGES - 1);
            cpa16(&s_x[ns][tid], xb + (k + STAGES - 1) * THREADS);
            cpa16(&s_t[ns][tid], tb + (k + STAGES - 1) * THREADS);
        }
        cpa_commit();   // commit every iter (possibly empty) keeps group math uniform

        // one LG2 per 4 elements: log2((1+e0)(1+e1)(1+e2)(1+e3))
        float e0 = __expf(-fabsf(xv.x));
        float e1 = __expf(-fabsf(xv.y));
        float a01 = 1.0f + e0;
        float p01 = __fmaf_rn(e1, a01, a01);       // (1+e0)(1+e1)
        float e2 = __expf(-fabsf(xv.z));
        float e3 = __expf(-fabsf(xv.w));
        float a23 = 1.0f + e2;
        float p23 = __fmaf_rn(e3, a23, a23);       // (1+e2)(1+e3)
        accL2 += __log2f(p01 * p23);

        // linear terms: Σ max(x,0) - x·t, two chains
        aL0 += fmaxf(xv.x, 0.0f);
        aL0  = __fmaf_rn(-xv.x, tv.x, aL0);
        aL1 += fmaxf(xv.y, 0.0f);
        aL1  = __fmaf_rn(-xv.y, tv.y, aL1);
        aL0 += fmaxf(xv.z, 0.0f);
        aL0  = __fmaf_rn(-xv.z, tv.z, aL0);
        aL1 += fmaxf(xv.w, 0.0f);
        aL1  = __fmaf_rn(-xv.w, tv.w, aL1);

        // bbox: per-column running max + per-row any
        cm0 = fmaxf(cm0, xv.x);
        cm1 = fmaxf(cm1, xv.y);
        cm2 = fmaxf(cm2, xv.z);
        cm3 = fmaxf(cm3, xv.w);
        float m4 = fmaxf(fmaxf(xv.x, xv.y), fmaxf(xv.z, xv.w));
        if (m4 > 0.0f) rmask |= (1u << k);
    }

    // Decode per-thread bbox contribution
    int minR, maxR, minC, maxC;
    {
        const int rb = rowBase + (tid >> 6);   // rows visited: rb + 4k, k=0..31
        if (rmask) {
            minR = rb + 4 * (__ffs(rmask) - 1);
            maxR = rb + 4 * (31 - __clz(rmask));
        } else { minR = INT_MAX; maxR = -1; }

        const int cb = (tid & 63) << 2;
        unsigned cmsk = (cm0 > 0.0f ? 1u : 0u) | (cm1 > 0.0f ? 2u : 0u)
                      | (cm2 > 0.0f ? 4u : 0u) | (cm3 > 0.0f ? 8u : 0u);
        if (cmsk) {
            minC = cb + (__ffs(cmsk) - 1);
            maxC = cb + (31 - __clz(cmsk));
        } else { minC = INT_MAX; maxC = -1; }
    }

    float seg = (aL0 + aL1) + LN2F * accL2;

    // ---- intra-warp reduction (shuffle) ----
    #pragma unroll
    for (int off = 16; off > 0; off >>= 1) {
        seg  += __shfl_xor_sync(0xFFFFFFFFu, seg,  off);
        minR  = min(minR, __shfl_xor_sync(0xFFFFFFFFu, minR, off));
        maxR  = max(maxR, __shfl_xor_sync(0xFFFFFFFFu, maxR, off));
        minC  = min(minC, __shfl_xor_sync(0xFFFFFFFFu, minC, off));
        maxC  = max(maxC, __shfl_xor_sync(0xFFFFFFFFu, maxC, off));
    }

    // ---- cross-warp reduction via smem (8 warps) ----
    __shared__ float s_seg[8];
    __shared__ int   s_mnR[8], s_mxR[8], s_mnC[8], s_mxC[8];
    const int wid = tid >> 5, lid = tid & 31;
    if (lid == 0) {
        s_seg[wid] = seg;
        s_mnR[wid] = minR; s_mxR[wid] = maxR;
        s_mnC[wid] = minC; s_mxC[wid] = maxC;
    }
    __syncthreads();
    if (tid == 0) {
        float rs = s_seg[0];
        int rmnR = s_mnR[0], rmxR = s_mxR[0], rmnC = s_mnC[0], rmxC = s_mxC[0];
        #pragma unroll
        for (int w = 1; w < 8; ++w) {
            rs   += s_seg[w];
            rmnR  = min(rmnR, s_mnR[w]); rmxR = max(rmxR, s_mxR[w]);
            rmnC  = min(rmnC, s_mnC[w]); rmxC = max(rmxC, s_mxC[w]);
        }
        g_seg[blk] = rs;
        g_box[blk] = make_int4(rmnR, rmxR, rmnC, rmxC);
    }

    // ---- last-block-finishes tail ----
    __shared__ bool s_isLast;
    __threadfence();
    if (tid == 0) {
        unsigned int c = atomicAdd(&g_count, 1u);
        s_isLast = (c == NBLOCKS - 1);
    }
    __syncthreads();
    if (!s_isLast) return;

    // Tail: thread s handles slice s (256 threads)
    const int s = tid;
    float segT = 0.0f;
    int mnR = INT_MAX, mxR = -1, mnC = INT_MAX, mxC = -1;
    #pragma unroll
    for (int p = 0; p < SPLIT; ++p) {
        int idx = s * SPLIT + p;
        segT += __ldcg(&g_seg[idx]);
        int4 b = __ldcg(&g_box[idx]);
        mnR = min(mnR, b.x); mxR = max(mxR, b.y);
        mnC = min(mnC, b.z); mxC = max(mxC, b.w);
    }

    float bx, by, bw, bh;
    if (mxR < 0) {                       // empty mask
        bx = 0.0f; by = 0.0f; bw = 256.0f; bh = 256.0f;
    } else {
        bx = (float)mnC; by = (float)mnR;
        bw = (float)(mxC - mnC); bh = (float)(mxR - mnR);
    }

    float pred[4] = {bx, by, bw, bh};
    float l = 0.0f;
    #pragma unroll
    for (int j = 0; j < 4; ++j) {
        float d  = pred[j] - tgt[s * 4 + j];
        float ad = fabsf(d);
        l += (ad < 1.0f) ? 0.5f * d * d : ad - 0.5f;
    }

    // reduce 256 lanes: warp shuffle + smem
    #pragma unroll
    for (int off = 16; off > 0; off >>= 1) {
        segT += __shfl_xor_sync(0xFFFFFFFFu, segT, off);
        l    += __shfl_xor_sync(0xFFFFFFFFu, l,    off);
    }
    __shared__ float t_seg[8], t_box[8];
    const int wid2 = tid >> 5, lid2 = tid & 31;
    if (lid2 == 0) { t_seg[wid2] = segT; t_box[wid2] = l; }
    __syncthreads();
    if (tid == 0) {
        float fs = 0.0f, fb = 0.0f;
        #pragma unroll
        for (int w = 0; w < 8; ++w) { fs += t_seg[w]; fb += t_box[w]; }
        out[0] = fs / TOTAL_ELEMS;
        out[1] = fb / NBOX_ELEMS;
        g_count = 0;                     // reset for next graph replay
    }
}

extern "C" void kernel_launch(void* const* d_in, const int* in_sizes, int n_in,
                              void* d_out, int out_size)
{
    const float4* x4 = (const float4*)d_in[0];   // model_output
    const float4* t4 = (const float4*)d_in[1];   // target_masks
    const float*  tb = (const float*)d_in[2];    // target_bboxes
    float* out = (float*)d_out;

    fused_kernel<<<NBLOCKS, THREADS>>>(x4, t4, tb, out);
}